// round 2
// baseline (speedup 1.0000x reference)
#include <cuda_runtime.h>

// Problem constants
#define DD 160
#define HH 192
#define WW 160
#define DHW (DD*HH*WW)          // 4,915,200
#define BB 2
#define CC 2

__global__ __launch_bounds__(256)
void warp3d_kernel(const float* __restrict__ x,
                   const float* __restrict__ flow,
                   float* __restrict__ out)
{
    int idx = blockIdx.x * blockDim.x + threadIdx.x;
    if (idx >= BB * DHW) return;

    int b = idx / DHW;
    int s = idx - b * DHW;
    int xw = s % WW;
    int t  = s / WW;
    int yh = t % HH;
    int zd = t / HH;

    const float* fb = flow + (size_t)b * 3 * DHW;
    float pz = (float)zd + fb[s];
    float py = (float)yh + fb[s + DHW];
    float px = (float)xw + fb[s + 2 * DHW];

    float z0f = floorf(pz), y0f = floorf(py), x0f = floorf(px);
    float fz = pz - z0f, fy = py - y0f, fx = px - x0f;
    int z0 = (int)z0f, y0 = (int)y0f, x0 = (int)x0f;
    int z1 = z0 + 1, y1 = y0 + 1, x1 = x0 + 1;

    // per-axis weights, zeroed when the corner index is out of bounds
    float wz0 = (z0 >= 0 && z0 < DD) ? (1.0f - fz) : 0.0f;
    float wz1 = (z1 >= 0 && z1 < DD) ? fz          : 0.0f;
    float wy0 = (y0 >= 0 && y0 < HH) ? (1.0f - fy) : 0.0f;
    float wy1 = (y1 >= 0 && y1 < HH) ? fy          : 0.0f;
    float wx0 = (x0 >= 0 && x0 < WW) ? (1.0f - fx) : 0.0f;
    float wx1 = (x1 >= 0 && x1 < WW) ? fx          : 0.0f;

    // clamped indices (value irrelevant when weight is 0, just keep in-bounds)
    int zc0 = min(max(z0, 0), DD - 1);
    int zc1 = min(max(z1, 0), DD - 1);
    int yc0 = min(max(y0, 0), HH - 1);
    int yc1 = min(max(y1, 0), HH - 1);
    int xc0 = min(max(x0, 0), WW - 1);
    int xc1 = min(max(x1, 0), WW - 1);

    const float* xb = x + (size_t)b * CC * DHW;

    int base00 = (zc0 * HH + yc0) * WW;
    int base01 = (zc0 * HH + yc1) * WW;
    int base10 = (zc1 * HH + yc0) * WW;
    int base11 = (zc1 * HH + yc1) * WW;

    float w000 = wz0 * wy0 * wx0;
    float w001 = wz0 * wy0 * wx1;
    float w010 = wz0 * wy1 * wx0;
    float w011 = wz0 * wy1 * wx1;
    float w100 = wz1 * wy0 * wx0;
    float w101 = wz1 * wy0 * wx1;
    float w110 = wz1 * wy1 * wx0;
    float w111 = wz1 * wy1 * wx1;

    int o000 = base00 + xc0, o001 = base00 + xc1;
    int o010 = base01 + xc0, o011 = base01 + xc1;
    int o100 = base10 + xc0, o101 = base10 + xc1;
    int o110 = base11 + xc0, o111 = base11 + xc1;

    // channel 0
    float a0 = 0.0f;
    a0 = fmaf(xb[o000], w000, a0);
    a0 = fmaf(xb[o001], w001, a0);
    a0 = fmaf(xb[o010], w010, a0);
    a0 = fmaf(xb[o011], w011, a0);
    a0 = fmaf(xb[o100], w100, a0);
    a0 = fmaf(xb[o101], w101, a0);
    a0 = fmaf(xb[o110], w110, a0);
    a0 = fmaf(xb[o111], w111, a0);

    // channel 1 (reuse indices/weights)
    const float* xb1 = xb + DHW;
    float a1 = 0.0f;
    a1 = fmaf(xb1[o000], w000, a1);
    a1 = fmaf(xb1[o001], w001, a1);
    a1 = fmaf(xb1[o010], w010, a1);
    a1 = fmaf(xb1[o011], w011, a1);
    a1 = fmaf(xb1[o100], w100, a1);
    a1 = fmaf(xb1[o101], w101, a1);
    a1 = fmaf(xb1[o110], w110, a1);
    a1 = fmaf(xb1[o111], w111, a1);

    float* ob = out + (size_t)b * CC * DHW;
    ob[s]        = a0;
    ob[s + DHW]  = a1;
}

extern "C" void kernel_launch(void* const* d_in, const int* in_sizes, int n_in,
                              void* d_out, int out_size)
{
    const float* x    = (const float*)d_in[0];
    const float* flow = (const float*)d_in[1];
    float* out        = (float*)d_out;

    const int N = BB * DHW;
    const int threads = 256;
    const int blocks = (N + threads - 1) / threads;
    warp3d_kernel<<<blocks, threads>>>(x, flow, out);
}